// round 17
// baseline (speedup 1.0000x reference)
#include <cuda_runtime.h>

#define BB    16
#define NN    128
#define FIN   8
#define SDIM  8
#define FO    64
#define KH    32
#define VROW  288          // padded V row stride in floats (272 used)
#define CAP   64           // max edges per destination (nnz ~13)

// g_V fully overwritten each call. g_pool accumulated by k_gemm, zero-restored
// by k_head (replay-safe).
__device__ float g_V   [BB * NN * VROW];   // [bn][ P(256) | Q(8) | x(8) | pad ]
__device__ float g_pool[BB * FO];

// ---------------------------------------------------------------------------
// k_build: grid 512, block 128 = 4 warps, ONE WARP PER DESTINATION.
// Lane l owns k=l: h_l computed locally, P[l][0..7] in registers.
// No parity split, no smem staging: V row written straight from registers.
// ---------------------------------------------------------------------------
__global__ void __launch_bounds__(128)
k_build(const float* __restrict__ A,
        const float* __restrict__ X,
        const float* __restrict__ E,
        const float* __restrict__ kn_w1,
        const float* __restrict__ kn_b1) {
    int t    = threadIdx.x;        // 0..127
    int w    = t >> 5;             // warp 0..3 = dest slot
    int lane = t & 31;
    int b    = blockIdx.x >> 5;    // 32 blocks per b
    int n    = (blockIdx.x & 31) * 4 + w;

    __shared__ alignas(16) float sw1[SDIM * KH];   // 1KB, [s][k]
    __shared__ alignas(16) float sb1[KH];
    __shared__ alignas(16) float sxb[NN * FIN];    // 4KB, X[b]
    __shared__ alignas(16) float sa [4][CAP];
    __shared__ alignas(16) short sn [4][CAP];

    for (int u = t; u < SDIM * KH; u += 128) sw1[u] = kn_w1[u];
    if (t < KH) sb1[t] = kn_b1[t];
    {
        const float4* xs = (const float4*)(X + (size_t)b * NN * FIN);
        for (int u = t; u < NN * FIN / 4; u += 128) ((float4*)sxb)[u] = xs[u];
    }
    __syncthreads();

    // warp-local compaction of row A[b,n,:] (contiguous float4 read)
    int cnt = 0;
    {
        const float4* Ar = (const float4*)(A + ((size_t)b * NN + n) * NN);
        float4 av = Ar[lane];                           // i = 4*lane .. +3
#pragma unroll
        for (int e = 0; e < 4; ++e) {
            float v = (e == 0) ? av.x : (e == 1) ? av.y : (e == 2) ? av.z : av.w;
            unsigned m = __ballot_sync(0xffffffffu, v != 0.f);
            if (v != 0.f) {
                int pos = cnt + __popc(m & ((1u << lane) - 1u));
                if (pos < CAP) { sa[w][pos] = v; sn[w][pos] = (short)(4 * lane + e); }
            }
            cnt += __popc(m);
        }
        if (cnt > CAP) cnt = CAP;
    }
    __syncwarp();

    float P[8] = {0.f, 0.f, 0.f, 0.f, 0.f, 0.f, 0.f, 0.f};
    float q[8] = {0.f, 0.f, 0.f, 0.f, 0.f, 0.f, 0.f, 0.f};
    const float* Erow = E + ((size_t)b * NN + n) * NN * SDIM;

    if (cnt > 0) {
        int   i = sn[w][0];
        float a = sa[w][0];
        const float4* e4 = (const float4*)(Erow + (size_t)i * SDIM);
        float4 e0 = e4[0], e1 = e4[1];

        for (int j = 0; j < cnt; ++j) {
            int jn = j + 1;
            int inext = 0; float anext = 0.f;
            float4 p0 = e0, p1 = e1;
            if (jn < cnt) {
                inext = sn[w][jn]; anext = sa[w][jn];
                const float4* pe = (const float4*)(Erow + (size_t)inext * SDIM);
                p0 = pe[0]; p1 = pe[1];
            }

            // h_k for k = lane: two 4-FMA chains then add
            float h0 = sb1[lane];
            h0 = fmaf(e0.x, sw1[0 * KH + lane], h0);
            h0 = fmaf(e0.y, sw1[1 * KH + lane], h0);
            h0 = fmaf(e0.z, sw1[2 * KH + lane], h0);
            h0 = fmaf(e0.w, sw1[3 * KH + lane], h0);
            float h1 = 0.f;
            h1 = fmaf(e1.x, sw1[4 * KH + lane], h1);
            h1 = fmaf(e1.y, sw1[5 * KH + lane], h1);
            h1 = fmaf(e1.z, sw1[6 * KH + lane], h1);
            h1 = fmaf(e1.w, sw1[7 * KH + lane], h1);
            float hv = fmaxf(h0 + h1, 0.f);
            float ah = a * hv;

            const float4* xp = (const float4*)(sxb + i * FIN);  // broadcast LDS
            float4 x0 = xp[0], x1 = xp[1];
            P[0] = fmaf(ah, x0.x, P[0]);  P[1] = fmaf(ah, x0.y, P[1]);
            P[2] = fmaf(ah, x0.z, P[2]);  P[3] = fmaf(ah, x0.w, P[3]);
            P[4] = fmaf(ah, x1.x, P[4]);  P[5] = fmaf(ah, x1.y, P[5]);
            P[6] = fmaf(ah, x1.z, P[6]);  P[7] = fmaf(ah, x1.w, P[7]);
            q[0] = fmaf(a, x0.x, q[0]);   q[1] = fmaf(a, x0.y, q[1]);
            q[2] = fmaf(a, x0.z, q[2]);   q[3] = fmaf(a, x0.w, q[3]);
            q[4] = fmaf(a, x1.x, q[4]);   q[5] = fmaf(a, x1.y, q[5]);
            q[6] = fmaf(a, x1.z, q[6]);   q[7] = fmaf(a, x1.w, q[7]);

            i = inext; a = anext; e0 = p0; e1 = p1;
        }
    }

    // write V row straight from registers (lane = k): vrow[lane*8 + f]
    float* vrow = g_V + ((size_t)b * NN + n) * VROW;
    ((float4*)(vrow + lane * 8))[0] = make_float4(P[0], P[1], P[2], P[3]);
    ((float4*)(vrow + lane * 8))[1] = make_float4(P[4], P[5], P[6], P[7]);
    if (lane == 0) {
#pragma unroll
        for (int f = 0; f < 8; ++f) vrow[256 + f] = q[f];   // Q identical on all lanes
    }
    if (lane < FIN) vrow[264 + lane] = sxb[n * FIN + lane]; // x
}

// ---------------------------------------------------------------------------
// k_gemm: grid 256 (b x 16 groups of 8 dests), block 256.
// Thread (og = t&15 -> o-quad, jq = t>>4 -> 17-row j slice) holds its W slice
// (17 x float4) in registers, loops 8 destinations. Single barrier epilogue.
// ---------------------------------------------------------------------------
__global__ void __launch_bounds__(256)
k_gemm(const float* __restrict__ kn_w2,
       const float* __restrict__ kn_b2,
       const float* __restrict__ root_w,
       const float* __restrict__ conv_b) {
    int t    = threadIdx.x;
    int w    = t >> 5;             // warp 0..7
    int lane = t & 31;
    int og   = t & 15;             // o = og*4 .. +4
    int jbase = (t >> 4) * 17;     // j slice [jbase, jbase+17)
    int b    = blockIdx.x >> 4;
    int n0   = (blockIdx.x & 15) * 8;

    __shared__ alignas(16) float sV    [8][VROW];      // 9KB
    __shared__ alignas(16) float s_part[8][8][FO];     // 16KB [dd][warp][o]

    // warp w loads dest w's V row (68 float4)
    {
        const float4* src = (const float4*)(g_V + ((size_t)b * NN + n0 + w) * VROW);
        for (int u = lane; u < 68; u += 32) ((float4*)sV[w])[u] = src[u];
    }

    // W slice into registers: rows j = jbase..jbase+16, columns og*4..+4
    float4 Wr[17];
#pragma unroll
    for (int jj = 0; jj < 17; ++jj) {
        int jg = jbase + jj;
        const float* src;
        if (jg < 256)      src = kn_w2  + jg * 64;
        else if (jg < 264) src = kn_b2  + (jg - 256) * 64;
        else               src = root_w + (jg - 264) * 64;
        Wr[jj] = ((const float4*)src)[og];
    }
    __syncthreads();

#pragma unroll
    for (int dd = 0; dd < 8; ++dd) {
        float4 acc = make_float4(0.f, 0.f, 0.f, 0.f);
        const float* V = sV[dd] + jbase;
#pragma unroll
        for (int jj = 0; jj < 17; ++jj) {
            float vj = V[jj];
            acc.x = fmaf(Wr[jj].x, vj, acc.x);
            acc.y = fmaf(Wr[jj].y, vj, acc.y);
            acc.z = fmaf(Wr[jj].z, vj, acc.z);
            acc.w = fmaf(Wr[jj].w, vj, acc.w);
        }
        // combine the two jq halves within this warp (lanes l and l^16)
        acc.x += __shfl_xor_sync(0xffffffffu, acc.x, 16);
        acc.y += __shfl_xor_sync(0xffffffffu, acc.y, 16);
        acc.z += __shfl_xor_sync(0xffffffffu, acc.z, 16);
        acc.w += __shfl_xor_sync(0xffffffffu, acc.w, 16);
        if (lane < 16) ((float4*)s_part[dd][w])[og] = acc;
    }
    __syncthreads();

    if (t < FO) {
        float cb = conv_b[t];
        float pool = 0.f;
#pragma unroll
        for (int dd = 0; dd < 8; ++dd) {
            float s = 0.f;
#pragma unroll
            for (int ww = 0; ww < 8; ++ww) s += s_part[dd][ww][t];
            pool += fmaxf(s + cb, 0.f);
        }
        atomicAdd(&g_pool[b * FO + t], pool);
    }
}

// ---------------------------------------------------------------------------
// k_head: grid B, 64 threads. Read g_pool (restore zero), /N, Dense(32,relu),
// Dense(1,sigmoid).
// ---------------------------------------------------------------------------
__global__ void k_head(const float* __restrict__ fc_w,
                       const float* __restrict__ fc_b,
                       const float* __restrict__ out_w,
                       const float* __restrict__ out_b,
                       float* __restrict__ out) {
    int b = blockIdx.x;
    int t = threadIdx.x;
    __shared__ float sfeat[FO];

    float v = g_pool[b * FO + t];
    g_pool[b * FO + t] = 0.f;          // restore zero for next call/replay
    sfeat[t] = v * (1.f / NN);
    __syncthreads();

    if (t < 32) {
        float f = fc_b[t];
#pragma unroll
        for (int o2 = 0; o2 < FO; ++o2) f = fmaf(sfeat[o2], fc_w[o2 * 32 + t], f);
        f = fmaxf(f, 0.f);
        float p = f * out_w[t];
#pragma unroll
        for (int off = 16; off > 0; off >>= 1)
            p += __shfl_xor_sync(0xffffffffu, p, off);
        if (t == 0) out[b] = 1.f / (1.f + expf(-(p + out_b[0])));
    }
}

// ---------------------------------------------------------------------------
// Inputs (metadata order): A, X, E, kn_w1, kn_b1, kn_w2, kn_b2, root_w, conv_b,
//                          fc_w, fc_b, out_w, out_b
// ---------------------------------------------------------------------------
extern "C" void kernel_launch(void* const* d_in, const int* in_sizes, int n_in,
                              void* d_out, int out_size) {
    const float* A      = (const float*)d_in[0];
    const float* X      = (const float*)d_in[1];
    const float* E      = (const float*)d_in[2];
    const float* kn_w1  = (const float*)d_in[3];
    const float* kn_b1  = (const float*)d_in[4];
    const float* kn_w2  = (const float*)d_in[5];
    const float* kn_b2  = (const float*)d_in[6];
    const float* root_w = (const float*)d_in[7];
    const float* conv_b = (const float*)d_in[8];
    const float* fc_w   = (const float*)d_in[9];
    const float* fc_b   = (const float*)d_in[10];
    const float* out_w  = (const float*)d_in[11];
    const float* out_b  = (const float*)d_in[12];
    float* out = (float*)d_out;

    k_build<<<512, 128>>>(A, X, E, kn_w1, kn_b1);
    k_gemm <<<256, 256>>>(kn_w2, kn_b2, root_w, conv_b);
    k_head <<<BB, 64>>>(fc_w, fc_b, out_w, out_b, out);
}